// round 15
// baseline (speedup 1.0000x reference)
#include <cuda_runtime.h>
#include <cuda_fp16.h>
#include <cstdint>

// ---------------- problem constants ----------------
#define E_DIM 256
#define I_DIM 35
#define M_TILE 128
#define THREADS 1024

// ---------------- smem layout (bytes) ----------------
#define SM_CONST  0                        // float[256]
#define SM_GAMMA  1024                     // float[256]
#define SM_BETA   2048                     // float[256]
#define SM_SRED   3072                     // float2[128][4] = 4096B
#define SM_A      7168                     // 4 chunks x 16384B (128m x 64k fp16, swizzled)
#define SM_W      (SM_A + 65536)           // 4 chunks x 32768B = 128KB (all W resident)
#define SMEM_TOTAL (SM_W + 131072)         // ~199KB -> 1 CTA/SM

#define W_CHUNK_BYTES 32768                // 256e x 64k x 2B
#define A_CHUNK_BYTES 16384                // 128m x 64k x 2B

// ---------------- device scratch ----------------
__device__ __align__(16) __half g_W[4 * 16384];        // [chunk][e][k] swizzled fp16
__device__ __align__(16) float g_BsumT[E_DIM * 36];    // [e][i] bias partials, padded to 36

// ---------------- helpers ----------------
__device__ __forceinline__ uint32_t smem_u32(const void* p) {
    uint32_t a; asm("{ .reg .u64 t; cvta.to.shared.u64 t, %1; cvt.u32.u64 %0, t; }" : "=r"(a) : "l"(p));
    return a;
}
__device__ __forceinline__ uint32_t swz(uint32_t off) { return off ^ ((off >> 3) & 0x70); }
__device__ __forceinline__ float dot4(float4 a, float4 b) {
    return a.x * b.x + a.y * b.y + a.z * b.z + a.w * b.w;
}
__device__ __forceinline__ uint32_t h2_as_u32(__half2 h) {
    uint32_t u; *reinterpret_cast<__half2*>(&u) = h; return u;
}
__device__ __forceinline__ void ldsm4(uint32_t (&r)[4], uint32_t addr) {
    asm volatile("ldmatrix.sync.aligned.m8n8.x4.shared.b16 {%0,%1,%2,%3}, [%4];"
                 : "=r"(r[0]), "=r"(r[1]), "=r"(r[2]), "=r"(r[3]) : "r"(addr));
}
__device__ __forceinline__ void mma_fp16(float (&c)[4], const uint32_t (&a)[4], uint32_t b0, uint32_t b1) {
    asm volatile("mma.sync.aligned.m16n8k16.row.col.f32.f16.f16.f32 "
                 "{%0,%1,%2,%3}, {%4,%5,%6,%7}, {%8,%9}, {%0,%1,%2,%3};"
                 : "+f"(c[0]), "+f"(c[1]), "+f"(c[2]), "+f"(c[3])
                 : "r"(a[0]), "r"(a[1]), "r"(a[2]), "r"(a[3]), "r"(b0), "r"(b1));
}
#define CP_ASYNC16(dst, src) \
    asm volatile("cp.async.cg.shared.global [%0], [%1], 16;" :: "r"(dst), "l"(src))
#define CP_COMMIT() asm volatile("cp.async.commit_group;" ::: "memory")
#define CP_WAIT(n)  asm volatile("cp.async.wait_group %0;" :: "n"(n) : "memory")

// ---------------- precompute: fold Wf, emit fp16 swizzled W [e][k] ----------------
__device__ __forceinline__ void store_w(int k, int e, float v) {
    int chunk = k >> 6;
    uint32_t sw = swz((uint32_t)(e * 128 + (k & 63) * 2));
    *reinterpret_cast<__half*>(reinterpret_cast<char*>(g_W) + chunk * W_CHUNK_BYTES + sw) = __float2half(v);
}

__device__ __forceinline__ void fold_one(
    int e, int i, int lane, float4 f0, float4 f1,
    const float* __restrict__ Wd, const float* __restrict__ bd,
    const float* __restrict__ Wc, const float* __restrict__ bc,
    const float* __restrict__ Wr, const float* __restrict__ br,
    const float* __restrict__ emb) {
    const int half = lane >> 4;
    const int c = (lane & 15) * 4;

    const float4* w0p = half ? reinterpret_cast<const float4*>(Wc + i * 64 + c)
                             : reinterpret_cast<const float4*>(Wd + i * 64 + c);
    const float4* b0p = half ? reinterpret_cast<const float4*>(bc + i * 64 + c)
                             : reinterpret_cast<const float4*>(bd + i * 64 + c);
    float a0 = dot4(*w0p, f0);
    float pb = dot4(*b0p, f0);

    float a1 = 0.f, pe0 = 0.f, pe1 = 0.f, pe2 = 0.f, pe3 = 0.f;
    if (half == 0) {
        a1 = dot4(*reinterpret_cast<const float4*>(Wr + i * 64 + c), f1);
        pb += dot4(*reinterpret_cast<const float4*>(br + i * 64 + c), f1);
    } else {
        const float* eb = emb + (size_t)(i * 4) * 64 + c;
        pe0 = dot4(*reinterpret_cast<const float4*>(eb), f1);
        pe1 = dot4(*reinterpret_cast<const float4*>(eb + 64), f1);
        pe2 = dot4(*reinterpret_cast<const float4*>(eb + 128), f1);
        pe3 = dot4(*reinterpret_cast<const float4*>(eb + 192), f1);
    }

    #pragma unroll
    for (int o = 8; o; o >>= 1) {
        a0  += __shfl_down_sync(0xffffffffu, a0, o);
        a1  += __shfl_down_sync(0xffffffffu, a1, o);
        pe0 += __shfl_down_sync(0xffffffffu, pe0, o);
        pe1 += __shfl_down_sync(0xffffffffu, pe1, o);
        pe2 += __shfl_down_sync(0xffffffffu, pe2, o);
        pe3 += __shfl_down_sync(0xffffffffu, pe3, o);
    }
    #pragma unroll
    for (int o = 16; o; o >>= 1) pb += __shfl_down_sync(0xffffffffu, pb, o);

    if (lane == 0) {
        store_w(i, e, a0);            // depth
        store_w(70 + i, e, a1);       // rlen
        g_BsumT[e * 36 + i] = pb;
    }
    if (lane == 16) {
        store_w(35 + i, e, a0);       // cov
        store_w(105 + 4 * i + 0, e, pe0);
        store_w(105 + 4 * i + 1, e, pe1);
        store_w(105 + 4 * i + 2, e, pe2);
        store_w(105 + 4 * i + 3, e, pe3);
    }
}

// warp per (e, i-pair): i = 2*ip, 2*ip+1 -> 4 Wf LDG.128 in flight per lane
__global__ __launch_bounds__(256)
void precompute_kernel(const float* __restrict__ Wd, const float* __restrict__ bd,
                       const float* __restrict__ Wc, const float* __restrict__ bc,
                       const float* __restrict__ Wr, const float* __restrict__ br,
                       const float* __restrict__ emb, const float* __restrict__ Wf) {
    if (blockIdx.x == 0) {                 // zero-pad rows k=245..255 and Bsum pad
        int e = threadIdx.x;
        for (int k = 245; k < 256; k++) store_w(k, e, 0.0f);
        g_BsumT[e * 36 + 35] = 0.0f;
    }

    int gw = (blockIdx.x * blockDim.x + threadIdx.x) >> 5;
    int lane = threadIdx.x & 31;
    if (gw >= E_DIM * 18) return;
    int e = gw / 18;
    int ip = gw - e * 18;
    int i0 = ip * 2;
    const float* wf = Wf + (size_t)e * (I_DIM * 256) + (size_t)i0 * 256;

    // issue all Wf loads up front (MLP = 4)
    float4 fa0 = *reinterpret_cast<const float4*>(wf + lane * 4);
    float4 fa1 = *reinterpret_cast<const float4*>(wf + 128 + lane * 4);
    float4 fb0, fb1;
    const bool has2 = (i0 + 1) < I_DIM;
    if (has2) {
        fb0 = *reinterpret_cast<const float4*>(wf + 256 + lane * 4);
        fb1 = *reinterpret_cast<const float4*>(wf + 384 + lane * 4);
    }

    fold_one(e, i0, lane, fa0, fa1, Wd, bd, Wc, bc, Wr, br, emb);
    if (has2)
        fold_one(e, i0 + 1, lane, fb0, fb1, Wd, bd, Wc, bc, Wr, br, emb);
}

// ---------------- staging helpers (A chunk stride = 16384B) ----------------
__device__ __forceinline__ void stage_onehot(char* sm, int m, int i, float v) {
    int ri = (int)v;
    int r = ri >= 0 ? ri : (ri == -1 ? 2 : 3);
    int kk = 105 + 4 * i + r;
    uint32_t sw = swz((uint32_t)(m * 128 + (kk & 63) * 2));
    *reinterpret_cast<uint16_t*>(sm + SM_A + (kk >> 6) * A_CHUNK_BYTES + sw) = 0x3C00;  // fp16 1.0
}

__device__ __forceinline__ void stage_f4(char* sm, int m, int fi, float4 f) {
    const int k0 = fi * 4;
    if (fi <= 25) {
        uint2 h;
        h.x = h2_as_u32(__floats2half2_rn(f.x, f.y));
        h.y = h2_as_u32(__floats2half2_rn(f.z, f.w));
        uint32_t sw = swz((uint32_t)(m * 128 + (k0 & 63) * 2));
        *reinterpret_cast<uint2*>(sm + SM_A + (k0 >> 6) * A_CHUNK_BYTES + sw) = h;
    } else if (fi == 26) {
        uint32_t sw = swz((uint32_t)(m * 128 + (104 & 63) * 2));
        *reinterpret_cast<__half*>(sm + SM_A + A_CHUNK_BYTES + sw) = __float2half(f.x);
        stage_onehot(sm, m, 0, f.y);
        stage_onehot(sm, m, 1, f.z);
        stage_onehot(sm, m, 2, f.w);
    } else {
        const int i0 = k0 - 105;
        stage_onehot(sm, m, i0 + 0, f.x);
        stage_onehot(sm, m, i0 + 1, f.y);
        stage_onehot(sm, m, i0 + 2, f.z);
        stage_onehot(sm, m, i0 + 3, f.w);
    }
}

// ---------------- main: single-pass fp16 HMMA GEMM + fused LayerNorm/ReLU ----------------
// 32 warps: 8 mwarps x 4 nwarps; warp tile 16m x 64n.
// Prologue order: metadata LDGs FIRST (registers), then W cp.async -> both streams overlap.
__global__ __launch_bounds__(THREADS, 1)
void main_kernel(const float* __restrict__ metadata,
                 const float* __restrict__ bf,
                 const float* __restrict__ gamma,
                 const float* __restrict__ beta,
                 float* __restrict__ out) {
    extern __shared__ __align__(1024) char sm[];
    const uint32_t sbase = smem_u32(sm);
    const int tid = threadIdx.x;
    const int wid = tid >> 5;
    const int lane = tid & 31;
    const int b0 = blockIdx.x * M_TILE;

    const int nwarp = wid & 3;            // n_base = nwarp*64
    const int mwarp = wid >> 2;           // m_base = mwarp*16
    const int n_base = nwarp * 64;
    const int m_base = mwarp * 16;

    // 1) metadata LDGs first: warp-per-4-rows, lane-per-float4 into registers
    float4 fv[4], fw[4];
    {
        #pragma unroll
        for (int rr = 0; rr < 4; rr++) {
            const float4* row = reinterpret_cast<const float4*>(metadata + (size_t)(b0 + wid * 4 + rr) * 140);
            fv[rr] = row[lane];
            if (lane < 3) fw[rr] = row[32 + lane];
        }
    }

    // 2) W cp.async: one group PER CHUNK (32KB = 2 x 16B per thread)
    {
        const char* src = reinterpret_cast<const char*>(g_W);
        #pragma unroll
        for (int c = 0; c < 4; c++) {
            uint32_t coff = c * W_CHUNK_BYTES;
            CP_ASYNC16(sbase + SM_W + coff + tid * 16,         src + coff + tid * 16);
            CP_ASYNC16(sbase + SM_W + coff + tid * 16 + 16384, src + coff + tid * 16 + 16384);
            CP_COMMIT();
        }
    }

    // 3) zero A chunks 1-3 (chunk 0 fully overwritten by scalars k<64)
    {
        uint4 z = make_uint4(0, 0, 0, 0);
        uint4* p = reinterpret_cast<uint4*>(sm + SM_A + A_CHUNK_BYTES);
        #pragma unroll
        for (int it = 0; it < 3; it++) p[tid + it * THREADS] = z;
    }
    // 4) const[e] (threads 0-255) ; gamma/beta copy (threads 256-511)
    if (tid < 256) {
        int e = tid;
        const float4* bp = reinterpret_cast<const float4*>(&g_BsumT[e * 36]);
        float s = bf[e];
        #pragma unroll
        for (int q = 0; q < 9; q++) {
            float4 t = bp[q];
            s += (t.x + t.y) + (t.z + t.w);
        }
        *reinterpret_cast<float*>(sm + SM_CONST + e * 4) = s;
    } else if (tid < 512) {
        int e = tid - 256;
        *reinterpret_cast<float*>(sm + SM_GAMMA + e * 4) = gamma[e];
        *reinterpret_cast<float*>(sm + SM_BETA + e * 4) = beta[e];
    }

    // 5) stage A from registers
    {
        #pragma unroll
        for (int rr = 0; rr < 4; rr++) {
            int m = wid * 4 + rr;
            stage_f4(sm, m, lane, fv[rr]);
            if (lane < 3) stage_f4(sm, m, 32 + lane, fw[rr]);
        }
    }

    // barrier 1: A staged + const/gb written + W chunk0 resident
    CP_WAIT(3);
    __syncthreads();

    // ---- mainloop ----
    float acc[8][4];
    #pragma unroll
    for (int nt = 0; nt < 8; nt++)
        #pragma unroll
        for (int q = 0; q < 4; q++) acc[nt][q] = 0.f;

    const int r8 = lane & 7, j = lane >> 3;
    const uint32_t ka = (j >> 1) * 16;        // A k-byte offset
    const uint32_t kb = (j & 1) * 16;         // B k-byte offset
    const uint32_t aRowB = (uint32_t)(m_base + (j & 1) * 8 + r8) * 128;
    uint32_t bRowB[4];
    #pragma unroll
    for (int np = 0; np < 4; np++) bRowB[np] = (uint32_t)(n_base + np * 16 + (j >> 1) * 8 + r8) * 128;

    // chunk 0 (guaranteed resident)
    {
        const uint32_t wbuf = sbase + SM_W;
        const uint32_t aBase = sbase + SM_A;
        #pragma unroll
        for (int kk = 0; kk < 4; kk++) {
            uint32_t a[4];
            ldsm4(a, aBase + swz(aRowB + kk * 32 + ka));
            #pragma unroll
            for (int np = 0; np < 4; np++) {
                uint32_t b[4];
                ldsm4(b, wbuf + swz(bRowB[np] + kk * 32 + kb));
                mma_fp16(acc[np * 2 + 0], a, b[0], b[1]);
                mma_fp16(acc[np * 2 + 1], a, b[2], b[3]);
            }
        }
    }

    // barrier 2: chunks 1-3 resident (fetch overlapped chunk-0 compute)
    CP_WAIT(0);
    __syncthreads();

    #pragma unroll
    for (int p = 1; p < 4; p++) {
        const uint32_t wbuf = sbase + SM_W + p * W_CHUNK_BYTES;
        const uint32_t aBase = sbase + SM_A + p * A_CHUNK_BYTES;
        #pragma unroll
        for (int kk = 0; kk < 4; kk++) {
            uint32_t a[4];
            ldsm4(a, aBase + swz(aRowB + kk * 32 + ka));
            #pragma unroll
            for (int np = 0; np < 4; np++) {
                uint32_t b[4];
                ldsm4(b, wbuf + swz(bRowB[np] + kk * 32 + kb));
                mma_fp16(acc[np * 2 + 0], a, b[0], b[1]);
                mma_fp16(acc[np * 2 + 1], a, b[2], b[3]);
            }
        }
    }

    // ---- epilogue: add const, per-row LayerNorm + ReLU, store ----
    const float* cst = reinterpret_cast<const float*>(sm + SM_CONST);
    const float* gmm = reinterpret_cast<const float*>(sm + SM_GAMMA);
    const float* bta = reinterpret_cast<const float*>(sm + SM_BETA);
    float2* sred = reinterpret_cast<float2*>(sm + SM_SRED);
    const int g = lane >> 2, t = lane & 3;

    float s1[2] = {0, 0}, s2[2] = {0, 0};   // h = 0: row m_base+g, h = 1: +8
    #pragma unroll
    for (int nt = 0; nt < 8; nt++) {
        int col0 = n_base + nt * 8 + t * 2;
        float c0 = cst[col0], c1 = cst[col0 + 1];
        #pragma unroll
        for (int h = 0; h < 2; h++) {
            float v0 = acc[nt][h * 2 + 0] + c0;
            float v1 = acc[nt][h * 2 + 1] + c1;
            acc[nt][h * 2 + 0] = v0;
            acc[nt][h * 2 + 1] = v1;
            s1[h] += v0 + v1;
            s2[h] += v0 * v0 + v1 * v1;
        }
    }
    #pragma unroll
    for (int h = 0; h < 2; h++) {
        s1[h] += __shfl_xor_sync(0xffffffffu, s1[h], 1);
        s1[h] += __shfl_xor_sync(0xffffffffu, s1[h], 2);
        s2[h] += __shfl_xor_sync(0xffffffffu, s2[h], 1);
        s2[h] += __shfl_xor_sync(0xffffffffu, s2[h], 2);
    }
    if (t < 2) {
        int row = m_base + g + t * 8;
        sred[row * 4 + nwarp] = make_float2(s1[t], s2[t]);
    }
    __syncthreads();

    float mu[2], rs[2];
    #pragma unroll
    for (int h = 0; h < 2; h++) {
        int row = m_base + g + h * 8;
        float2 p0 = sred[row * 4 + 0], p1 = sred[row * 4 + 1];
        float2 p2 = sred[row * 4 + 2], p3 = sred[row * 4 + 3];
        float S1 = (p0.x + p1.x) + (p2.x + p3.x);
        float S2 = (p0.y + p1.y) + (p2.y + p3.y);
        mu[h] = S1 * (1.0f / E_DIM);
        float var = S2 * (1.0f / E_DIM) - mu[h] * mu[h];
        rs[h] = rsqrtf(var + 1e-5f);
    }

    #pragma unroll
    for (int h = 0; h < 2; h++) {
        size_t grow = (size_t)(b0 + m_base + h * 8 + g);
        #pragma unroll
        for (int nt = 0; nt < 8; nt++) {
            int col0 = n_base + nt * 8 + t * 2;
            float y0 = fmaxf(0.f, (acc[nt][h * 2 + 0] - mu[h]) * rs[h] * gmm[col0] + bta[col0]);
            float y1 = fmaxf(0.f, (acc[nt][h * 2 + 1] - mu[h]) * rs[h] * gmm[col0 + 1] + bta[col0 + 1]);
            *reinterpret_cast<float2*>(out + grow * E_DIM + col0) = make_float2(y0, y1);
        }
    }
}

// ---------------- launch ----------------
extern "C" void kernel_launch(void* const* d_in, const int* in_sizes, int n_in,
                              void* d_out, int out_size) {
    const float* metadata = (const float*)d_in[0];
    const float* Wd    = (const float*)d_in[1];
    const float* bd    = (const float*)d_in[2];
    const float* Wc    = (const float*)d_in[3];
    const float* bc    = (const float*)d_in[4];
    const float* Wr    = (const float*)d_in[5];
    const float* br    = (const float*)d_in[6];
    const float* emb   = (const float*)d_in[7];
    const float* Wf    = (const float*)d_in[8];
    const float* bf    = (const float*)d_in[9];
    const float* gamma = (const float*)d_in[10];
    const float* beta  = (const float*)d_in[11];
    float* out = (float*)d_out;

    int B = in_sizes[0] / 140;

    static bool attr_set = false;
    if (!attr_set) {
        cudaFuncSetAttribute(main_kernel, cudaFuncAttributeMaxDynamicSharedMemorySize, SMEM_TOTAL);
        attr_set = true;
    }

    int pre_blocks = (E_DIM * 18 * 32 + 255) / 256;   // warp per (e, i-pair)
    precompute_kernel<<<pre_blocks, 256>>>(Wd, bd, Wc, bc, Wr, br, emb, Wf);
    main_kernel<<<B / M_TILE, THREADS, SMEM_TOTAL>>>(metadata, bf, gamma, beta, out);
}

// round 16
// speedup vs baseline: 1.0767x; 1.0767x over previous
#include <cuda_runtime.h>
#include <cuda_fp16.h>
#include <cstdint>

// ---------------- problem constants ----------------
#define E_DIM 256
#define I_DIM 35
#define M_TILE 128
#define THREADS 1024

// ---------------- smem layout (bytes) ----------------
#define SM_CONST  0                        // float[256]
#define SM_GAMMA  1024                     // float[256]
#define SM_BETA   2048                     // float[256]
#define SM_SRED   3072                     // float2[128][4] = 4096B
#define SM_A      7168                     // 4 chunks x 16384B (128m x 64k fp16, swizzled)
#define SM_W      (SM_A + 65536)           // 4 chunks x 32768B = 128KB (all W resident)
#define SMEM_TOTAL (SM_W + 131072)         // ~199KB -> 1 CTA/SM

#define W_CHUNK_BYTES 32768                // 256e x 64k x 2B
#define A_CHUNK_BYTES 16384                // 128m x 64k x 2B

// ---------------- device scratch ----------------
__device__ __align__(16) __half g_W[4 * 16384];        // [chunk][e][k] swizzled fp16
__device__ __align__(16) float g_BsumT[E_DIM * 36];    // [e][i] bias partials, padded to 36

// ---------------- helpers ----------------
__device__ __forceinline__ uint32_t smem_u32(const void* p) {
    uint32_t a; asm("{ .reg .u64 t; cvta.to.shared.u64 t, %1; cvt.u32.u64 %0, t; }" : "=r"(a) : "l"(p));
    return a;
}
__device__ __forceinline__ uint32_t swz(uint32_t off) { return off ^ ((off >> 3) & 0x70); }
__device__ __forceinline__ float dot4(float4 a, float4 b) {
    return a.x * b.x + a.y * b.y + a.z * b.z + a.w * b.w;
}
__device__ __forceinline__ uint32_t h2_as_u32(__half2 h) {
    uint32_t u; *reinterpret_cast<__half2*>(&u) = h; return u;
}
__device__ __forceinline__ void ldsm4(uint32_t (&r)[4], uint32_t addr) {
    asm volatile("ldmatrix.sync.aligned.m8n8.x4.shared.b16 {%0,%1,%2,%3}, [%4];"
                 : "=r"(r[0]), "=r"(r[1]), "=r"(r[2]), "=r"(r[3]) : "r"(addr));
}
__device__ __forceinline__ void mma_fp16(float (&c)[4], const uint32_t (&a)[4], uint32_t b0, uint32_t b1) {
    asm volatile("mma.sync.aligned.m16n8k16.row.col.f32.f16.f16.f32 "
                 "{%0,%1,%2,%3}, {%4,%5,%6,%7}, {%8,%9}, {%0,%1,%2,%3};"
                 : "+f"(c[0]), "+f"(c[1]), "+f"(c[2]), "+f"(c[3])
                 : "r"(a[0]), "r"(a[1]), "r"(a[2]), "r"(a[3]), "r"(b0), "r"(b1));
}
#define CP_ASYNC16(dst, src) \
    asm volatile("cp.async.cg.shared.global [%0], [%1], 16;" :: "r"(dst), "l"(src))
#define CP_COMMIT() asm volatile("cp.async.commit_group;" ::: "memory")
#define CP_WAIT(n)  asm volatile("cp.async.wait_group %0;" :: "n"(n) : "memory")

// ---------------- precompute: fold Wf, emit fp16 swizzled W [e][k] (R12 form) ----------------
__device__ __forceinline__ void store_w(int k, int e, float v) {
    int chunk = k >> 6;
    uint32_t sw = swz((uint32_t)(e * 128 + (k & 63) * 2));
    *reinterpret_cast<__half*>(reinterpret_cast<char*>(g_W) + chunk * W_CHUNK_BYTES + sw) = __float2half(v);
}

__global__ __launch_bounds__(256)
void precompute_kernel(const float* __restrict__ Wd, const float* __restrict__ bd,
                       const float* __restrict__ Wc, const float* __restrict__ bc,
                       const float* __restrict__ Wr, const float* __restrict__ br,
                       const float* __restrict__ emb, const float* __restrict__ Wf) {
    if (blockIdx.x == 0) {                 // zero-pad rows k=245..255 and Bsum pad
        int e = threadIdx.x;
        for (int k = 245; k < 256; k++) store_w(k, e, 0.0f);
        g_BsumT[e * 36 + 35] = 0.0f;
    }

    int gw = (blockIdx.x * blockDim.x + threadIdx.x) >> 5;
    int lane = threadIdx.x & 31;
    if (gw >= E_DIM * I_DIM) return;
    int e = gw / I_DIM;
    int i = gw - e * I_DIM;
    const float* wf = Wf + (size_t)e * (I_DIM * 256) + (size_t)i * 256;

    const int half = lane >> 4;
    const int c = (lane & 15) * 4;

    float4 f0 = *reinterpret_cast<const float4*>(wf + lane * 4);
    const float4* w0p = half ? reinterpret_cast<const float4*>(Wc + i * 64 + c)
                             : reinterpret_cast<const float4*>(Wd + i * 64 + c);
    const float4* b0p = half ? reinterpret_cast<const float4*>(bc + i * 64 + c)
                             : reinterpret_cast<const float4*>(bd + i * 64 + c);
    float a0 = dot4(*w0p, f0);
    float pb = dot4(*b0p, f0);

    float4 f1 = *reinterpret_cast<const float4*>(wf + 128 + lane * 4);
    float a1 = 0.f, pe0 = 0.f, pe1 = 0.f, pe2 = 0.f, pe3 = 0.f;
    if (half == 0) {
        a1 = dot4(*reinterpret_cast<const float4*>(Wr + i * 64 + c), f1);
        pb += dot4(*reinterpret_cast<const float4*>(br + i * 64 + c), f1);
    } else {
        const float* eb = emb + (size_t)(i * 4) * 64 + c;
        pe0 = dot4(*reinterpret_cast<const float4*>(eb), f1);
        pe1 = dot4(*reinterpret_cast<const float4*>(eb + 64), f1);
        pe2 = dot4(*reinterpret_cast<const float4*>(eb + 128), f1);
        pe3 = dot4(*reinterpret_cast<const float4*>(eb + 192), f1);
    }

    #pragma unroll
    for (int o = 8; o; o >>= 1) {
        a0  += __shfl_down_sync(0xffffffffu, a0, o);
        a1  += __shfl_down_sync(0xffffffffu, a1, o);
        pe0 += __shfl_down_sync(0xffffffffu, pe0, o);
        pe1 += __shfl_down_sync(0xffffffffu, pe1, o);
        pe2 += __shfl_down_sync(0xffffffffu, pe2, o);
        pe3 += __shfl_down_sync(0xffffffffu, pe3, o);
    }
    #pragma unroll
    for (int o = 16; o; o >>= 1) pb += __shfl_down_sync(0xffffffffu, pb, o);

    if (lane == 0) {
        store_w(i, e, a0);            // depth
        store_w(70 + i, e, a1);       // rlen
        g_BsumT[e * 36 + i] = pb;
    }
    if (lane == 16) {
        store_w(35 + i, e, a0);       // cov
        store_w(105 + 4 * i + 0, e, pe0);
        store_w(105 + 4 * i + 1, e, pe1);
        store_w(105 + 4 * i + 2, e, pe2);
        store_w(105 + 4 * i + 3, e, pe3);
    }
}

// ---------------- staging helpers (A chunk stride = 16384B) ----------------
__device__ __forceinline__ void stage_onehot(char* sm, int m, int i, float v) {
    int ri = (int)v;
    int r = ri >= 0 ? ri : (ri == -1 ? 2 : 3);
    int kk = 105 + 4 * i + r;
    uint32_t sw = swz((uint32_t)(m * 128 + (kk & 63) * 2));
    *reinterpret_cast<uint16_t*>(sm + SM_A + (kk >> 6) * A_CHUNK_BYTES + sw) = 0x3C00;  // fp16 1.0
}

__device__ __forceinline__ void stage_f4(char* sm, int m, int fi, float4 f) {
    const int k0 = fi * 4;
    if (fi <= 25) {
        uint2 h;
        h.x = h2_as_u32(__floats2half2_rn(f.x, f.y));
        h.y = h2_as_u32(__floats2half2_rn(f.z, f.w));
        uint32_t sw = swz((uint32_t)(m * 128 + (k0 & 63) * 2));
        *reinterpret_cast<uint2*>(sm + SM_A + (k0 >> 6) * A_CHUNK_BYTES + sw) = h;
    } else if (fi == 26) {
        uint32_t sw = swz((uint32_t)(m * 128 + (104 & 63) * 2));
        *reinterpret_cast<__half*>(sm + SM_A + A_CHUNK_BYTES + sw) = __float2half(f.x);
        stage_onehot(sm, m, 0, f.y);
        stage_onehot(sm, m, 1, f.z);
        stage_onehot(sm, m, 2, f.w);
    } else {
        const int i0 = k0 - 105;
        stage_onehot(sm, m, i0 + 0, f.x);
        stage_onehot(sm, m, i0 + 1, f.y);
        stage_onehot(sm, m, i0 + 2, f.z);
        stage_onehot(sm, m, i0 + 3, f.w);
    }
}

// ---------------- main: single-pass fp16 HMMA GEMM + fused LayerNorm/ReLU ----------------
// 32 warps: 8 mwarps x 4 nwarps; warp tile 16m x 64n. (R14/R15 form, best main)
__global__ __launch_bounds__(THREADS, 1)
void main_kernel(const float* __restrict__ metadata,
                 const float* __restrict__ bf,
                 const float* __restrict__ gamma,
                 const float* __restrict__ beta,
                 float* __restrict__ out) {
    extern __shared__ __align__(1024) char sm[];
    const uint32_t sbase = smem_u32(sm);
    const int tid = threadIdx.x;
    const int wid = tid >> 5;
    const int lane = tid & 31;
    const int b0 = blockIdx.x * M_TILE;

    const int nwarp = wid & 3;            // n_base = nwarp*64
    const int mwarp = wid >> 2;           // m_base = mwarp*16
    const int n_base = nwarp * 64;
    const int m_base = mwarp * 16;

    // 1) metadata LDGs first: warp-per-4-rows, lane-per-float4 into registers
    float4 fv[4], fw[4];
    {
        #pragma unroll
        for (int rr = 0; rr < 4; rr++) {
            const float4* row = reinterpret_cast<const float4*>(metadata + (size_t)(b0 + wid * 4 + rr) * 140);
            fv[rr] = row[lane];
            if (lane < 3) fw[rr] = row[32 + lane];
        }
    }

    // 2) W cp.async: one group PER CHUNK (32KB = 2 x 16B per thread)
    {
        const char* src = reinterpret_cast<const char*>(g_W);
        #pragma unroll
        for (int c = 0; c < 4; c++) {
            uint32_t coff = c * W_CHUNK_BYTES;
            CP_ASYNC16(sbase + SM_W + coff + tid * 16,         src + coff + tid * 16);
            CP_ASYNC16(sbase + SM_W + coff + tid * 16 + 16384, src + coff + tid * 16 + 16384);
            CP_COMMIT();
        }
    }

    // 3) zero A chunks 1-3 (chunk 0 fully overwritten by scalars k<64)
    {
        uint4 z = make_uint4(0, 0, 0, 0);
        uint4* p = reinterpret_cast<uint4*>(sm + SM_A + A_CHUNK_BYTES);
        #pragma unroll
        for (int it = 0; it < 3; it++) p[tid + it * THREADS] = z;
    }
    // 4) const[e] (threads 0-255) ; gamma/beta copy (threads 256-511)
    if (tid < 256) {
        int e = tid;
        const float4* bp = reinterpret_cast<const float4*>(&g_BsumT[e * 36]);
        float s = bf[e];
        #pragma unroll
        for (int q = 0; q < 9; q++) {
            float4 t = bp[q];
            s += (t.x + t.y) + (t.z + t.w);
        }
        *reinterpret_cast<float*>(sm + SM_CONST + e * 4) = s;
    } else if (tid < 512) {
        int e = tid - 256;
        *reinterpret_cast<float*>(sm + SM_GAMMA + e * 4) = gamma[e];
        *reinterpret_cast<float*>(sm + SM_BETA + e * 4) = beta[e];
    }

    // 5) stage A from registers
    {
        #pragma unroll
        for (int rr = 0; rr < 4; rr++) {
            int m = wid * 4 + rr;
            stage_f4(sm, m, lane, fv[rr]);
            if (lane < 3) stage_f4(sm, m, 32 + lane, fw[rr]);
        }
    }

    // barrier 1: A staged + const/gb written + W chunk0 resident
    CP_WAIT(3);
    __syncthreads();

    // ---- mainloop ----
    float acc[8][4];
    #pragma unroll
    for (int nt = 0; nt < 8; nt++)
        #pragma unroll
        for (int q = 0; q < 4; q++) acc[nt][q] = 0.f;

    const int r8 = lane & 7, j = lane >> 3;
    const uint32_t ka = (j >> 1) * 16;        // A k-byte offset
    const uint32_t kb = (j & 1) * 16;         // B k-byte offset
    const uint32_t aRowB = (uint32_t)(m_base + (j & 1) * 8 + r8) * 128;
    uint32_t bRowB[4];
    #pragma unroll
    for (int np = 0; np < 4; np++) bRowB[np] = (uint32_t)(n_base + np * 16 + (j >> 1) * 8 + r8) * 128;

    // chunk 0 (guaranteed resident)
    {
        const uint32_t wbuf = sbase + SM_W;
        const uint32_t aBase = sbase + SM_A;
        #pragma unroll
        for (int kk = 0; kk < 4; kk++) {
            uint32_t a[4];
            ldsm4(a, aBase + swz(aRowB + kk * 32 + ka));
            #pragma unroll
            for (int np = 0; np < 4; np++) {
                uint32_t b[4];
                ldsm4(b, wbuf + swz(bRowB[np] + kk * 32 + kb));
                mma_fp16(acc[np * 2 + 0], a, b[0], b[1]);
                mma_fp16(acc[np * 2 + 1], a, b[2], b[3]);
            }
        }
    }

    // barrier 2: chunks 1-3 resident (fetch overlapped chunk-0 compute)
    CP_WAIT(0);
    __syncthreads();

    #pragma unroll
    for (int p = 1; p < 4; p++) {
        const uint32_t wbuf = sbase + SM_W + p * W_CHUNK_BYTES;
        const uint32_t aBase = sbase + SM_A + p * A_CHUNK_BYTES;
        #pragma unroll
        for (int kk = 0; kk < 4; kk++) {
            uint32_t a[4];
            ldsm4(a, aBase + swz(aRowB + kk * 32 + ka));
            #pragma unroll
            for (int np = 0; np < 4; np++) {
                uint32_t b[4];
                ldsm4(b, wbuf + swz(bRowB[np] + kk * 32 + kb));
                mma_fp16(acc[np * 2 + 0], a, b[0], b[1]);
                mma_fp16(acc[np * 2 + 1], a, b[2], b[3]);
            }
        }
    }

    // ---- epilogue: add const, per-row LayerNorm + ReLU, store ----
    const float* cst = reinterpret_cast<const float*>(sm + SM_CONST);
    const float* gmm = reinterpret_cast<const float*>(sm + SM_GAMMA);
    const float* bta = reinterpret_cast<const float*>(sm + SM_BETA);
    float2* sred = reinterpret_cast<float2*>(sm + SM_SRED);
    const int g = lane >> 2, t = lane & 3;

    float s1[2] = {0, 0}, s2[2] = {0, 0};   // h = 0: row m_base+g, h = 1: +8
    #pragma unroll
    for (int nt = 0; nt < 8; nt++) {
        int col0 = n_base + nt * 8 + t * 2;
        float c0 = cst[col0], c1 = cst[col0 + 1];
        #pragma unroll
        for (int h = 0; h < 2; h++) {
            float v0 = acc[nt][h * 2 + 0] + c0;
            float v1 = acc[nt][h * 2 + 1] + c1;
            acc[nt][h * 2 + 0] = v0;
            acc[nt][h * 2 + 1] = v1;
            s1[h] += v0 + v1;
            s2[h] += v0 * v0 + v1 * v1;
        }
    }
    #pragma unroll
    for (int h = 0; h < 2; h++) {
        s1[h] += __shfl_xor_sync(0xffffffffu, s1[h], 1);
        s1[h] += __shfl_xor_sync(0xffffffffu, s1[h], 2);
        s2[h] += __shfl_xor_sync(0xffffffffu, s2[h], 1);
        s2[h] += __shfl_xor_sync(0xffffffffu, s2[h], 2);
    }
    if (t < 2) {
        int row = m_base + g + t * 8;
        sred[row * 4 + nwarp] = make_float2(s1[t], s2[t]);
    }
    __syncthreads();

    float mu[2], rs[2];
    #pragma unroll
    for (int h = 0; h < 2; h++) {
        int row = m_base + g + h * 8;
        float2 p0 = sred[row * 4 + 0], p1 = sred[row * 4 + 1];
        float2 p2 = sred[row * 4 + 2], p3 = sred[row * 4 + 3];
        float S1 = (p0.x + p1.x) + (p2.x + p3.x);
        float S2 = (p0.y + p1.y) + (p2.y + p3.y);
        mu[h] = S1 * (1.0f / E_DIM);
        float var = S2 * (1.0f / E_DIM) - mu[h] * mu[h];
        rs[h] = rsqrtf(var + 1e-5f);
    }

    #pragma unroll
    for (int h = 0; h < 2; h++) {
        size_t grow = (size_t)(b0 + m_base + h * 8 + g);
        #pragma unroll
        for (int nt = 0; nt < 8; nt++) {
            int col0 = n_base + nt * 8 + t * 2;
            float y0 = fmaxf(0.f, (acc[nt][h * 2 + 0] - mu[h]) * rs[h] * gmm[col0] + bta[col0]);
            float y1 = fmaxf(0.f, (acc[nt][h * 2 + 1] - mu[h]) * rs[h] * gmm[col0 + 1] + bta[col0 + 1]);
            *reinterpret_cast<float2*>(out + grow * E_DIM + col0) = make_float2(y0, y1);
        }
    }
}

// ---------------- launch ----------------
extern "C" void kernel_launch(void* const* d_in, const int* in_sizes, int n_in,
                              void* d_out, int out_size) {
    const float* metadata = (const float*)d_in[0];
    const float* Wd    = (const float*)d_in[1];
    const float* bd    = (const float*)d_in[2];
    const float* Wc    = (const float*)d_in[3];
    const float* bc    = (const float*)d_in[4];
    const float* Wr    = (const float*)d_in[5];
    const float* br    = (const float*)d_in[6];
    const float* emb   = (const float*)d_in[7];
    const float* Wf    = (const float*)d_in[8];
    const float* bf    = (const float*)d_in[9];
    const float* gamma = (const float*)d_in[10];
    const float* beta  = (const float*)d_in[11];
    float* out = (float*)d_out;

    int B = in_sizes[0] / 140;

    static bool attr_set = false;
    if (!attr_set) {
        cudaFuncSetAttribute(main_kernel, cudaFuncAttributeMaxDynamicSharedMemorySize, SMEM_TOTAL);
        attr_set = true;
    }

    int pre_blocks = (E_DIM * I_DIM * 32 + 255) / 256;   // warp per (e,i), R12 form
    precompute_kernel<<<pre_blocks, 256>>>(Wd, bd, Wc, bc, Wr, br, emb, Wf);
    main_kernel<<<B / M_TILE, THREADS, SMEM_TOTAL>>>(metadata, bf, gamma, beta, out);
}